// round 13
// baseline (speedup 1.0000x reference)
#include <cuda_runtime.h>
#include <cuda_bf16.h>

// ConeProjection: out[b,k] = P[k]^T * sigma[b] * P[k]
//   sigma[a][c] = (vn·w_a)(vn·w_c) - alpha*(w_a·w_c)
//   w0 = R[:,0], w1 = R[:,1], w2 = t - eyes, vn = v/max(||v||,1e-14)
//   P[k] = ((ki-6)/6, (kj-6)/6, 1),  k = 13*ki + kj
//
// R11 (FFMA2 pass-pairs, pre-duplicated coefficient pairs in smem) with the
// geometry register footprint cut 30 -> 12 regs: only packed X,Y are kept and
// the quadratic is evaluated as x*(c0x+c4) + (y*(c1y+c3x+c5) + c2), still
// 5 fma.rn.f32x2 per pass-pair. __launch_bounds__(256,5) -> ~48 regs,
// 5 blocks/SM resident (occ ~50%) to hide store-drain + LDG latency that
// R11 exposed at occ 40%.

#define K_GRID  169
#define NB      16            // batches per warp
#define WARPS   8             // warps per block
#define THREADS (WARPS * 32)

__device__ __forceinline__ unsigned long long pack2f(float lo, float hi) {
    unsigned long long d;
    asm("mov.b64 %0, {%1, %2};" : "=l"(d) : "f"(lo), "f"(hi));
    return d;
}
__device__ __forceinline__ unsigned long long fma2(unsigned long long a,
                                                   unsigned long long b,
                                                   unsigned long long c) {
    unsigned long long d;
    asm("fma.rn.f32x2 %0, %1, %2, %3;" : "=l"(d) : "l"(a), "l"(b), "l"(c));
    return d;
}
__device__ __forceinline__ void unpack2f(unsigned long long s, float& lo, float& hi) {
    asm("mov.b64 {%0, %1}, %2;" : "=f"(lo), "=f"(hi) : "l"(s));
}

__global__ __launch_bounds__(THREADS, 5)
void cone_projection_kernel(const float* __restrict__ eyes,
                            const float* __restrict__ v,
                            const float* __restrict__ R,
                            const float* __restrict__ t,
                            const float* __restrict__ alpha,
                            float* __restrict__ out,
                            int B)
{
    // per batch, 3 float4: (c0,c0,c1,c1), (c3,c3,c4,c4), (c5,c5,c2,c2)
    __shared__ float4 scoef[WARPS * NB * 3];

    const int lane = threadIdx.x & 31;
    const int wid  = threadIdx.x >> 5;
    const long long base_b = ((long long)blockIdx.x * WARPS + wid) * NB;

    // --- Packed per-thread coords for pass-pair pp: elements
    //     k0 = lane + 64*pp (lo), k1 = k0 + 32 (hi); pp = 0..2 (12 regs) ---
    unsigned long long X[3], Y[3];
    #pragma unroll
    for (int pp = 0; pp < 3; ++pp) {
        float xv[2], yv[2];
        #pragma unroll
        for (int h = 0; h < 2; ++h) {
            const int k  = lane + 64 * pp + 32 * h;   // k1 may exceed 168: store predicated off
            const int ki = (k * 79) >> 10;            // k/13, exact for k < 169
            const int kj = k - 13 * ki;
            xv[h] = (float)(ki - 6) * (1.0f / 6.0f);
            yv[h] = (float)(kj - 6) * (1.0f / 6.0f);
        }
        X[pp] = pack2f(xv[0], xv[1]);
        Y[pp] = pack2f(yv[0], yv[1]);
    }

    // --- Phase A: lanes 0..15 build duplicated coefficient pairs ---
    if (lane < NB) {
        const long long b = base_b + lane;
        if (b < B) {
            float vx = v[b * 3 + 0];
            float vy = v[b * 3 + 1];
            float vz = v[b * 3 + 2];
            float n  = fmaxf(sqrtf(vx * vx + vy * vy + vz * vz), 1e-14f);
            float inv = 1.0f / n;
            vx *= inv; vy *= inv; vz *= inv;

            const float a = alpha[b];

            const float* Rb = R + b * 9;
            const float w0x = Rb[0], w0y = Rb[3], w0z = Rb[6];   // R[:,0]
            const float w1x = Rb[1], w1y = Rb[4], w1z = Rb[7];   // R[:,1]
            const float w2x = t[b * 3 + 0] - eyes[b * 3 + 0];
            const float w2y = t[b * 3 + 1] - eyes[b * 3 + 1];
            const float w2z = t[b * 3 + 2] - eyes[b * 3 + 2];

            const float d0 = vx * w0x + vy * w0y + vz * w0z;
            const float d1 = vx * w1x + vy * w1y + vz * w1z;
            const float d2 = vx * w2x + vy * w2y + vz * w2z;

            const float c0 = d0 * d0 - a * (w0x * w0x + w0y * w0y + w0z * w0z); // x^2
            const float c1 = d1 * d1 - a * (w1x * w1x + w1y * w1y + w1z * w1z); // y^2
            const float c2 = d2 * d2 - a * (w2x * w2x + w2y * w2y + w2z * w2z); // 1
            const float c3 = 2.0f * (d0 * d1 - a * (w0x * w1x + w0y * w1y + w0z * w1z)); // xy
            const float c4 = 2.0f * (d0 * d2 - a * (w0x * w2x + w0y * w2y + w0z * w2z)); // x
            const float c5 = 2.0f * (d1 * d2 - a * (w1x * w2x + w1y * w2y + w1z * w2z)); // y

            const int s = (wid * NB + lane) * 3;
            scoef[s]     = make_float4(c0, c0, c1, c1);
            scoef[s + 1] = make_float4(c3, c3, c4, c4);
            scoef[s + 2] = make_float4(c5, c5, c2, c2);
        }
    }
    __syncwarp();

    // --- Phase B: 16 batches x (3 broadcast LDS.128 + 3 x (5 FFMA2 + 2 STG)) ---
    const ulonglong2* sc2 = reinterpret_cast<const ulonglong2*>(scoef);

    #pragma unroll 4
    for (int bt = 0; bt < NB; ++bt) {
        const long long b = base_b + bt;
        if (b >= B) break;

        const int s = (wid * NB + bt) * 3;
        const ulonglong2 q0 = sc2[s];       // (c0,c0) , (c1,c1)
        const ulonglong2 q1 = sc2[s + 1];   // (c3,c3) , (c4,c4)
        const ulonglong2 q2 = sc2[s + 2];   // (c5,c5) , (c2,c2)

        float* o = out + b * (long long)K_GRID + lane;

        #pragma unroll
        for (int pp = 0; pp < 3; ++pp) {
            // r = x*(c0*x + c4) + (y*(c1*y + c3*x + c5) + c2), packed f32x2
            unsigned long long u = fma2(q0.x, X[pp], q1.y);   // c0*x + c4
            unsigned long long w = fma2(q1.x, X[pp], q2.x);   // c3*x + c5
            w = fma2(q0.y, Y[pp], w);                         // + c1*y
            unsigned long long sacc = fma2(Y[pp], w, q2.y);   // y*w + c2
            unsigned long long r = fma2(X[pp], u, sacc);      // + x*u
            float rlo, rhi;
            unpack2f(r, rlo, rhi);
            __stcs(&o[64 * pp], rlo);                 // pass 2*pp   (always valid)
            if (pp < 2 || lane < K_GRID - 160)        // pass 5: k = 160+lane < 169
                __stcs(&o[64 * pp + 32], rhi);        // pass 2*pp+1
        }
    }
}

extern "C" void kernel_launch(void* const* d_in, const int* in_sizes, int n_in,
                              void* d_out, int out_size) {
    const float* eyes  = (const float*)d_in[0];
    const float* v     = (const float*)d_in[1];
    const float* R     = (const float*)d_in[2];
    const float* t     = (const float*)d_in[3];
    const float* alpha = (const float*)d_in[4];
    float* out = (float*)d_out;

    const int B = in_sizes[4];                            // alpha: B elements
    const int warp_groups = (B + NB - 1) / NB;            // 8192 for B=131072
    const int blocks = (warp_groups + WARPS - 1) / WARPS; // 1024

    cone_projection_kernel<<<blocks, THREADS>>>(eyes, v, R, t, alpha, out, B);
}